// round 14
// baseline (speedup 1.0000x reference)
#include <cuda_runtime.h>
#include <math.h>

#define BATCH   256
#define D_INNER 5120
#define DT_RANK 160
#define NSTATE  16
#define NCOLS   192           // 160 (W_delta) + 16 (W_B) + 16 (W_C)

#define MT    16              // batch tile (gemm1)
#define KC1   64              // K chunk for gemm1
#define NKC   (D_INNER / KC1) // 80
#define NMT   (BATCH / MT)    // 16

#define DT_MT 32              // m-tile for k_dt
#define DT_NT 128             // d-tile for k_dt
#define DT_KB 16              // W_dt smem chunk rows

typedef unsigned long long u64;

// packed f32x2 helpers -------------------------------------------------------
__device__ __forceinline__ u64 pfma(u64 a, u64 b, u64 c) {
    u64 d;
    asm("fma.rn.f32x2 %0, %1, %2, %3;" : "=l"(d) : "l"(a), "l"(b), "l"(c));
    return d;
}
__device__ __forceinline__ u64 pk(float lo, float hi) {
    u64 r;
    asm("mov.b64 %0, {%1, %2};" : "=l"(r) : "f"(lo), "f"(hi));
    return r;
}
__device__ __forceinline__ float2 upk(u64 p) {
    float2 v;
    asm("mov.b64 {%0, %1}, %2;" : "=f"(v.x), "=f"(v.y) : "l"(p));
    return v;
}

// Scratch (allocation-free rule: __device__ globals)
__device__ float g_part[NKC * BATCH * NCOLS];   // 15.7 MB partials
__device__ float g_T  [BATCH * DT_RANK];
__device__ float g_Bp [BATCH * NSTATE];
__device__ float g_C  [BATCH * NSTATE];
__device__ float g_A  [D_INNER * NSTATE];       // -exp(A_log)
__device__ float g_dt [BATCH * D_INNER];        // softplus output

// ---------------------------------------------------------------------------
// Kernel 1: partial GEMM  P = x[mtile, kchunk] @ [W_delta | W_B | W_C]
// grid (16, 80), block 192 (thread = output column). Packed even/odd-k accs.
// ---------------------------------------------------------------------------
__global__ __launch_bounds__(192)
void k_gemm1(const float* __restrict__ x,
             const float* __restrict__ Wd,
             const float* __restrict__ Wb,
             const float* __restrict__ Wc)
{
    __shared__ __align__(16) float xs[MT * KC1];   // 4 KB, m-major
    const int m0  = blockIdx.x * MT;
    const int k0  = blockIdx.y * KC1;
    const int tid = threadIdx.x;

    for (int i = tid; i < MT * (KC1 / 4); i += 192)
        ((float4*)xs)[i] =
            *(const float4*)(x + (size_t)(m0 + i / (KC1 / 4)) * D_INNER
                               + k0 + (i % (KC1 / 4)) * 4);
    __syncthreads();

    const float* wptr;
    int wstride;
    if (tid < DT_RANK) {
        wptr = Wd + (size_t)k0 * DT_RANK + tid;                wstride = DT_RANK;
    } else if (tid < DT_RANK + NSTATE) {
        wptr = Wb + (size_t)k0 * NSTATE + (tid - DT_RANK);     wstride = NSTATE;
    } else {
        wptr = Wc + (size_t)k0 * NSTATE + (tid - DT_RANK - NSTATE); wstride = NSTATE;
    }

    u64 acc[MT];   // lanes: (even-k, odd-k) partials
    #pragma unroll
    for (int m = 0; m < MT; m++) acc[m] = 0ull;

    float w0 = wptr[0], w1 = wptr[wstride], w2 = wptr[2 * wstride], w3 = wptr[3 * wstride];

    #pragma unroll 2
    for (int k = 0; k < KC1; k += 4) {
        const float* wn = wptr + 4 * wstride;
        float n0 = w0, n1 = w1, n2 = w2, n3 = w3;
        if (k + 4 < KC1) {
            n0 = wn[0]; n1 = wn[wstride]; n2 = wn[2 * wstride]; n3 = wn[3 * wstride];
        }
        const u64 wp01 = pk(w0, w1);
        const u64 wp23 = pk(w2, w3);
        #pragma unroll
        for (int m = 0; m < MT; m++) {
            // 16B from xs row m at offset k: floats k..k+3
            ulonglong2 xv = *(const ulonglong2*)(xs + m * KC1 + k);
            acc[m] = pfma(xv.x, wp01, acc[m]);
            acc[m] = pfma(xv.y, wp23, acc[m]);
        }
        w0 = n0; w1 = n1; w2 = n2; w3 = n3; wptr = wn;
    }

    float* pout = g_part + ((size_t)blockIdx.y * BATCH + m0) * NCOLS + tid;
    #pragma unroll
    for (int m = 0; m < MT; m++) {
        float2 v = upk(acc[m]);
        pout[(size_t)m * NCOLS] = v.x + v.y;
    }
}

// ---------------------------------------------------------------------------
// Kernel 2: reduce 80 K-chunk partials -> T / Bp / C
// ---------------------------------------------------------------------------
__global__ __launch_bounds__(256)
void k_reduce()
{
    int idx = blockIdx.x * 256 + threadIdx.x;
    if (idx >= BATCH * NCOLS) return;
    int row = idx / NCOLS;
    int n   = idx % NCOLS;
    float s = 0.f;
    #pragma unroll
    for (int c = 0; c < NKC; c++)
        s += g_part[((size_t)c * BATCH + row) * NCOLS + n];
    if (n < DT_RANK)               g_T [row * DT_RANK + n] = s;
    else if (n < DT_RANK + NSTATE) g_Bp[row * NSTATE + (n - DT_RANK)] = s;
    else                           g_C [row * NSTATE + (n - DT_RANK - NSTATE)] = s;
}

// ---------------------------------------------------------------------------
// Kernel 3: A = -exp(A_log)
// ---------------------------------------------------------------------------
__global__ __launch_bounds__(256)
void k_prep(const float* __restrict__ A_log)
{
    int idx = blockIdx.x * 256 + threadIdx.x;
    if (idx < D_INNER * NSTATE) g_A[idx] = -__expf(A_log[idx]);
}

// ---------------------------------------------------------------------------
// Kernel 4: dt = softplus(T @ W_dt + b_dt)
// grid (8, 40), block 256. Block tile 32m x 128d. Thread 4m x 4d (packed d).
// Per k: 4 broadcast LDS32 (T) + 4 dup-movs + 1 LDS128 (W) + 8 pfma.
// W_dt double-buffered in 16-row chunks. smem = 20 + 16 = 36 KB.
// ---------------------------------------------------------------------------
__global__ __launch_bounds__(256)
void k_dt(const float* __restrict__ Wdt, const float* __restrict__ b_dt)
{
    __shared__ __align__(16) float Ts[DT_MT * DT_RANK];       // 20 KB
    __shared__ __align__(16) float ws[2][DT_KB * DT_NT];      // 2 x 8 KB
    const int m0  = blockIdx.x * DT_MT;
    const int d0  = blockIdx.y * DT_NT;
    const int tid = threadIdx.x;
    const int mg  = tid >> 5;          // 0..7 -> rows 4mg .. 4mg+3
    const int ng  = tid & 31;          // cols 4ng .. 4ng+3

    for (int i = tid; i < DT_MT * DT_RANK / 4; i += 256)
        ((float4*)Ts)[i] = ((const float4*)(g_T + (size_t)m0 * DT_RANK))[i];

    // preload W chunk 0
    for (int i = tid; i < DT_KB * (DT_NT / 4); i += 256)
        ((float4*)ws[0])[i] =
            *(const float4*)(Wdt + (size_t)(i / (DT_NT / 4)) * D_INNER
                                 + d0 + (i % (DT_NT / 4)) * 4);
    __syncthreads();

    u64 acc[4][2];
    #pragma unroll
    for (int a = 0; a < 4; a++) { acc[a][0] = 0ull; acc[a][1] = 0ull; }

    #pragma unroll
    for (int kc = 0; kc < DT_RANK / DT_KB; kc++) {
        const int buf = kc & 1;
        if (kc + 1 < DT_RANK / DT_KB) {
            for (int i = tid; i < DT_KB * (DT_NT / 4); i += 256)
                ((float4*)ws[buf ^ 1])[i] =
                    *(const float4*)(Wdt + (size_t)((kc + 1) * DT_KB + i / (DT_NT / 4)) * D_INNER
                                         + d0 + (i % (DT_NT / 4)) * 4);
        }
        const float* t0p = Ts + (4 * mg + 0) * DT_RANK + kc * DT_KB;
        const float* t1p = Ts + (4 * mg + 1) * DT_RANK + kc * DT_KB;
        const float* t2p = Ts + (4 * mg + 2) * DT_RANK + kc * DT_KB;
        const float* t3p = Ts + (4 * mg + 3) * DT_RANK + kc * DT_KB;
        const float* wb  = ws[buf] + ng * 4;
        #pragma unroll
        for (int k = 0; k < DT_KB; k++) {
            ulonglong2 wv = *(const ulonglong2*)(wb + k * DT_NT);   // 4 d-values
            u64 tp0 = pk(t0p[k], t0p[k]);
            u64 tp1 = pk(t1p[k], t1p[k]);
            u64 tp2 = pk(t2p[k], t2p[k]);
            u64 tp3 = pk(t3p[k], t3p[k]);
            acc[0][0] = pfma(tp0, wv.x, acc[0][0]);
            acc[0][1] = pfma(tp0, wv.y, acc[0][1]);
            acc[1][0] = pfma(tp1, wv.x, acc[1][0]);
            acc[1][1] = pfma(tp1, wv.y, acc[1][1]);
            acc[2][0] = pfma(tp2, wv.x, acc[2][0]);
            acc[2][1] = pfma(tp2, wv.y, acc[2][1]);
            acc[3][0] = pfma(tp3, wv.x, acc[3][0]);
            acc[3][1] = pfma(tp3, wv.y, acc[3][1]);
        }
        __syncthreads();
    }

    const float4 bd = *(const float4*)(b_dt + d0 + ng * 4);
    #pragma unroll
    for (int a = 0; a < 4; a++) {
        float2 lo = upk(acc[a][0]);
        float2 hi = upk(acc[a][1]);
        float4 z;
        z.x = lo.x + bd.x;
        z.y = lo.y + bd.y;
        z.z = hi.x + bd.z;
        z.w = hi.y + bd.w;
        z.x = (z.x > 20.f) ? z.x : log1pf(__expf(z.x));
        z.y = (z.y > 20.f) ? z.y : log1pf(__expf(z.y));
        z.z = (z.z > 20.f) ? z.z : log1pf(__expf(z.z));
        z.w = (z.w > 20.f) ? z.w : log1pf(__expf(z.w));
        *(float4*)(g_dt + (size_t)(m0 + 4 * mg + a) * D_INNER + d0 + ng * 4) = z;
    }
}

// ---------------------------------------------------------------------------
// Kernel 5: streaming epilogue. grid (8, 160), block 256.
// Block tile: 32 batches x 32 d. Thread: fixed d, 4 batches.
// ---------------------------------------------------------------------------
__global__ __launch_bounds__(256)
void k_epi(const float* __restrict__ x,
           const float* __restrict__ h,
           const float* __restrict__ Dv,
           float* __restrict__ out)
{
    __shared__ float Bsh[32 * NSTATE];
    __shared__ float Csh[32 * NSTATE];
    const int b0  = blockIdx.x * 32;
    const int d0  = blockIdx.y * 32;
    const int tid = threadIdx.x;
    const int dl  = tid & 31;
    const int bg  = tid >> 5;

    for (int i = tid; i < 32 * NSTATE; i += 256) {
        Bsh[i] = g_Bp[b0 * NSTATE + i];
        Csh[i] = g_C [b0 * NSTATE + i];
    }
    __syncthreads();

    const int d = d0 + dl;
    float a[NSTATE];
    #pragma unroll
    for (int q = 0; q < 4; q++) {
        float4 av = *(const float4*)(g_A + (size_t)d * NSTATE + q * 4);
        a[q * 4 + 0] = av.x; a[q * 4 + 1] = av.y;
        a[q * 4 + 2] = av.z; a[q * 4 + 3] = av.w;
    }
    const float Dd = Dv[d];

    #pragma unroll
    for (int i = 0; i < 4; i++) {
        const int b = b0 + bg * 4 + i;
        const size_t off = (size_t)b * D_INNER + d;
        const float dt  = g_dt[off];
        const float xv  = x[off];
        const float dtx = dt * xv;
        const float4* hp = (const float4*)(h + off * NSTATE);
        const int bb = (bg * 4 + i) * NSTATE;
        float y = 0.f;
        #pragma unroll
        for (int q = 0; q < 4; q++) {
            float4 h4 = hp[q];
            float hn;
            hn = fmaf(__expf(dt * a[q*4+0]), h4.x, dtx * Bsh[bb + q*4+0]); y = fmaf(hn, Csh[bb + q*4+0], y);
            hn = fmaf(__expf(dt * a[q*4+1]), h4.y, dtx * Bsh[bb + q*4+1]); y = fmaf(hn, Csh[bb + q*4+1], y);
            hn = fmaf(__expf(dt * a[q*4+2]), h4.z, dtx * Bsh[bb + q*4+2]); y = fmaf(hn, Csh[bb + q*4+2], y);
            hn = fmaf(__expf(dt * a[q*4+3]), h4.w, dtx * Bsh[bb + q*4+3]); y = fmaf(hn, Csh[bb + q*4+3], y);
        }
        out[off] = fmaf(xv, Dd, y);
    }
}

// ---------------------------------------------------------------------------
// Inputs (metadata order): x, h, W_delta, W_dt, b_dt, A_log, W_B, W_C, D
// ---------------------------------------------------------------------------
extern "C" void kernel_launch(void* const* d_in, const int* in_sizes, int n_in,
                              void* d_out, int out_size)
{
    const float* x      = (const float*)d_in[0];
    const float* h      = (const float*)d_in[1];
    const float* Wdelta = (const float*)d_in[2];
    const float* Wdt    = (const float*)d_in[3];
    const float* bdt    = (const float*)d_in[4];
    const float* Alog   = (const float*)d_in[5];
    const float* WB     = (const float*)d_in[6];
    const float* WC     = (const float*)d_in[7];
    const float* Dv     = (const float*)d_in[8];
    float* out = (float*)d_out;

    k_gemm1<<<dim3(NMT, NKC), 192>>>(x, Wdelta, WB, WC);
    k_prep<<<(D_INNER * NSTATE + 255) / 256, 256>>>(Alog);
    k_reduce<<<(BATCH * NCOLS + 255) / 256, 256>>>();
    k_dt<<<dim3(BATCH / DT_MT, D_INNER / DT_NT), 256>>>(Wdt, bdt);
    k_epi<<<dim3(BATCH / 32, D_INNER / 32), 256>>>(x, h, Dv, out);
}

// round 16
// speedup vs baseline: 1.2926x; 1.2926x over previous
#include <cuda_runtime.h>
#include <math.h>

#define BATCH   256
#define D_INNER 5120
#define DT_RANK 160
#define NSTATE  16
#define NCOLS   192           // 160 (W_delta) + 16 (W_B) + 16 (W_C)

#define MT    32              // batch tile (gemm1)
#define KC1   64              // K chunk for gemm1
#define NKC   (D_INNER / KC1) // 80
#define NMT   (BATCH / MT)    // 8

#define DT_MT 32              // m-tile for k_dt
#define DT_NT 128             // d-tile for k_dt
#define DT_KB 16              // W_dt smem chunk rows
#define DT_KH (DT_RANK / 2)   // 80: K half per block

// Scratch (allocation-free rule: __device__ globals)
__device__ float g_part[NKC * BATCH * NCOLS];     // 15.7 MB partials
__device__ float g_T  [BATCH * DT_RANK];
__device__ float g_Bp [BATCH * NSTATE];
__device__ float g_C  [BATCH * NSTATE];
__device__ float g_A  [D_INNER * NSTATE];         // -exp(A_log)
__device__ float g_dtp[2][BATCH * D_INNER];       // dt partial sums (2 K-halves)

// ---------------------------------------------------------------------------
// Kernel 1: partial GEMM  P = x[mtile, kchunk] @ [W_delta | W_B | W_C]
// grid (8, 80), block 192 (thread = output column). Scalar FMA + W prefetch.
// ---------------------------------------------------------------------------
__global__ __launch_bounds__(192)
void k_gemm1(const float* __restrict__ x,
             const float* __restrict__ Wd,
             const float* __restrict__ Wb,
             const float* __restrict__ Wc)
{
    __shared__ __align__(16) float xs[MT * KC1];   // 8 KB, m-major
    const int m0  = blockIdx.x * MT;
    const int k0  = blockIdx.y * KC1;
    const int tid = threadIdx.x;

    for (int i = tid; i < MT * (KC1 / 4); i += 192)
        ((float4*)xs)[i] =
            *(const float4*)(x + (size_t)(m0 + i / (KC1 / 4)) * D_INNER
                               + k0 + (i % (KC1 / 4)) * 4);
    __syncthreads();

    const float* wptr;
    int wstride;
    if (tid < DT_RANK) {
        wptr = Wd + (size_t)k0 * DT_RANK + tid;                wstride = DT_RANK;
    } else if (tid < DT_RANK + NSTATE) {
        wptr = Wb + (size_t)k0 * NSTATE + (tid - DT_RANK);     wstride = NSTATE;
    } else {
        wptr = Wc + (size_t)k0 * NSTATE + (tid - DT_RANK - NSTATE); wstride = NSTATE;
    }

    float acc[MT];
    #pragma unroll
    for (int m = 0; m < MT; m++) acc[m] = 0.f;

    float w0 = wptr[0], w1 = wptr[wstride], w2 = wptr[2 * wstride], w3 = wptr[3 * wstride];

    #pragma unroll 2
    for (int k = 0; k < KC1; k += 4) {
        const float* wn = wptr + 4 * wstride;
        float n0 = w0, n1 = w1, n2 = w2, n3 = w3;
        if (k + 4 < KC1) {
            n0 = wn[0]; n1 = wn[wstride]; n2 = wn[2 * wstride]; n3 = wn[3 * wstride];
        }
        #pragma unroll
        for (int m = 0; m < MT; m++) {
            float4 xv = *(const float4*)(xs + m * KC1 + k);
            float a = acc[m];
            a = fmaf(xv.x, w0, a);
            a = fmaf(xv.y, w1, a);
            a = fmaf(xv.z, w2, a);
            a = fmaf(xv.w, w3, a);
            acc[m] = a;
        }
        w0 = n0; w1 = n1; w2 = n2; w3 = n3; wptr = wn;
    }

    float* pout = g_part + ((size_t)blockIdx.y * BATCH + m0) * NCOLS + tid;
    #pragma unroll
    for (int m = 0; m < MT; m++) pout[(size_t)m * NCOLS] = acc[m];
}

// ---------------------------------------------------------------------------
// Kernel 2: reduce 80 K-chunk partials -> T / Bp / C
// ---------------------------------------------------------------------------
__global__ __launch_bounds__(256)
void k_reduce()
{
    int idx = blockIdx.x * 256 + threadIdx.x;
    if (idx >= BATCH * NCOLS) return;
    int row = idx / NCOLS;
    int n   = idx % NCOLS;
    float s = 0.f;
    #pragma unroll
    for (int c = 0; c < NKC; c++)
        s += g_part[((size_t)c * BATCH + row) * NCOLS + n];
    if (n < DT_RANK)               g_T [row * DT_RANK + n] = s;
    else if (n < DT_RANK + NSTATE) g_Bp[row * NSTATE + (n - DT_RANK)] = s;
    else                           g_C [row * NSTATE + (n - DT_RANK - NSTATE)] = s;
}

// ---------------------------------------------------------------------------
// Kernel 3: A = -exp(A_log)
// ---------------------------------------------------------------------------
__global__ __launch_bounds__(256)
void k_prep(const float* __restrict__ A_log)
{
    int idx = blockIdx.x * 256 + threadIdx.x;
    if (idx < D_INNER * NSTATE) g_A[idx] = -__expf(A_log[idx]);
}

// ---------------------------------------------------------------------------
// Kernel 4: dt partial = T[:, khalf] @ W_dt[khalf, :]   (no bias/softplus)
// grid (8, 40, 2), block 256. Block tile 32m x 128d x 80k. Thread 4m x 4d.
// Scalar FMA inner (R6-proven). W_dt double-buffered 16-row chunks.
// smem = 10 KB (T) + 16 KB (W) = 26 KB -> ~4.3 resident blocks/SM.
// ---------------------------------------------------------------------------
__global__ __launch_bounds__(256)
void k_dt(const float* __restrict__ Wdt)
{
    __shared__ __align__(16) float Ts[DT_MT * DT_KH];         // 10 KB
    __shared__ __align__(16) float ws[2][DT_KB * DT_NT];      // 2 x 8 KB
    const int m0  = blockIdx.x * DT_MT;
    const int d0  = blockIdx.y * DT_NT;
    const int kz  = blockIdx.z;            // K half: rows kz*80 .. kz*80+79
    const int kb0 = kz * DT_KH;
    const int tid = threadIdx.x;
    const int mg  = tid >> 5;              // 0..7 -> rows 4mg .. 4mg+3
    const int ng  = tid & 31;              // cols 4ng .. 4ng+3

    // T tile: rows m0..m0+31, cols kb0..kb0+79 (80 floats, float4-aligned)
    for (int i = tid; i < DT_MT * (DT_KH / 4); i += 256) {
        int row = i / (DT_KH / 4);
        int col = i % (DT_KH / 4);
        ((float4*)Ts)[row * (DT_KH / 4) + col] =
            *(const float4*)(g_T + (size_t)(m0 + row) * DT_RANK + kb0 + col * 4);
    }
    // preload W chunk 0
    for (int i = tid; i < DT_KB * (DT_NT / 4); i += 256)
        ((float4*)ws[0])[i] =
            *(const float4*)(Wdt + (size_t)(kb0 + i / (DT_NT / 4)) * D_INNER
                                 + d0 + (i % (DT_NT / 4)) * 4);
    __syncthreads();

    float acc[4][4];
    #pragma unroll
    for (int a = 0; a < 4; a++)
        #pragma unroll
        for (int b = 0; b < 4; b++) acc[a][b] = 0.f;

    #pragma unroll
    for (int kc = 0; kc < DT_KH / DT_KB; kc++) {
        const int buf = kc & 1;
        if (kc + 1 < DT_KH / DT_KB) {
            for (int i = tid; i < DT_KB * (DT_NT / 4); i += 256)
                ((float4*)ws[buf ^ 1])[i] =
                    *(const float4*)(Wdt + (size_t)(kb0 + (kc + 1) * DT_KB + i / (DT_NT / 4)) * D_INNER
                                         + d0 + (i % (DT_NT / 4)) * 4);
        }
        #pragma unroll
        for (int k = 0; k < DT_KB; k++) {
            float4 wv = ((const float4*)ws[buf])[k * (DT_NT / 4) + ng];
            float t0 = Ts[(4 * mg + 0) * DT_KH + kc * DT_KB + k];
            float t1 = Ts[(4 * mg + 1) * DT_KH + kc * DT_KB + k];
            float t2 = Ts[(4 * mg + 2) * DT_KH + kc * DT_KB + k];
            float t3 = Ts[(4 * mg + 3) * DT_KH + kc * DT_KB + k];
            acc[0][0] = fmaf(t0, wv.x, acc[0][0]);
            acc[0][1] = fmaf(t0, wv.y, acc[0][1]);
            acc[0][2] = fmaf(t0, wv.z, acc[0][2]);
            acc[0][3] = fmaf(t0, wv.w, acc[0][3]);
            acc[1][0] = fmaf(t1, wv.x, acc[1][0]);
            acc[1][1] = fmaf(t1, wv.y, acc[1][1]);
            acc[1][2] = fmaf(t1, wv.z, acc[1][2]);
            acc[1][3] = fmaf(t1, wv.w, acc[1][3]);
            acc[2][0] = fmaf(t2, wv.x, acc[2][0]);
            acc[2][1] = fmaf(t2, wv.y, acc[2][1]);
            acc[2][2] = fmaf(t2, wv.z, acc[2][2]);
            acc[2][3] = fmaf(t2, wv.w, acc[2][3]);
            acc[3][0] = fmaf(t3, wv.x, acc[3][0]);
            acc[3][1] = fmaf(t3, wv.y, acc[3][1]);
            acc[3][2] = fmaf(t3, wv.z, acc[3][2]);
            acc[3][3] = fmaf(t3, wv.w, acc[3][3]);
        }
        __syncthreads();
    }

    float* outp = g_dtp[kz];
    #pragma unroll
    for (int a = 0; a < 4; a++) {
        float4 z;
        z.x = acc[a][0]; z.y = acc[a][1]; z.z = acc[a][2]; z.w = acc[a][3];
        *(float4*)(outp + (size_t)(m0 + 4 * mg + a) * D_INNER + d0 + ng * 4) = z;
    }
}

// ---------------------------------------------------------------------------
// Kernel 5: streaming epilogue. grid (8, 160), block 256.
// dt = softplus(p0 + p1 + b_dt) computed inline.
// Block tile: 32 batches x 32 d. Thread: fixed d, 4 batches.
// ---------------------------------------------------------------------------
__global__ __launch_bounds__(256)
void k_epi(const float* __restrict__ x,
           const float* __restrict__ h,
           const float* __restrict__ b_dt,
           const float* __restrict__ Dv,
           float* __restrict__ out)
{
    __shared__ float Bsh[32 * NSTATE];
    __shared__ float Csh[32 * NSTATE];
    const int b0  = blockIdx.x * 32;
    const int d0  = blockIdx.y * 32;
    const int tid = threadIdx.x;
    const int dl  = tid & 31;
    const int bg  = tid >> 5;

    for (int i = tid; i < 32 * NSTATE; i += 256) {
        Bsh[i] = g_Bp[b0 * NSTATE + i];
        Csh[i] = g_C [b0 * NSTATE + i];
    }
    __syncthreads();

    const int d = d0 + dl;
    float a[NSTATE];
    #pragma unroll
    for (int q = 0; q < 4; q++) {
        float4 av = *(const float4*)(g_A + (size_t)d * NSTATE + q * 4);
        a[q * 4 + 0] = av.x; a[q * 4 + 1] = av.y;
        a[q * 4 + 2] = av.z; a[q * 4 + 3] = av.w;
    }
    const float Dd = Dv[d];
    const float bd = b_dt[d];

    #pragma unroll
    for (int i = 0; i < 4; i++) {
        const int b = b0 + bg * 4 + i;
        const size_t off = (size_t)b * D_INNER + d;
        const float z   = g_dtp[0][off] + g_dtp[1][off] + bd;
        const float dt  = (z > 20.f) ? z : log1pf(__expf(z));
        const float xv  = x[off];
        const float dtx = dt * xv;
        const float4* hp = (const float4*)(h + off * NSTATE);
        const int bb = (bg * 4 + i) * NSTATE;
        float y = 0.f;
        #pragma unroll
        for (int q = 0; q < 4; q++) {
            float4 h4 = hp[q];
            float hn;
            hn = fmaf(__expf(dt * a[q*4+0]), h4.x, dtx * Bsh[bb + q*4+0]); y = fmaf(hn, Csh[bb + q*4+0], y);
            hn = fmaf(__expf(dt * a[q*4+1]), h4.y, dtx * Bsh[bb + q*4+1]); y = fmaf(hn, Csh[bb + q*4+1], y);
            hn = fmaf(__expf(dt * a[q*4+2]), h4.z, dtx * Bsh[bb + q*4+2]); y = fmaf(hn, Csh[bb + q*4+2], y);
            hn = fmaf(__expf(dt * a[q*4+3]), h4.w, dtx * Bsh[bb + q*4+3]); y = fmaf(hn, Csh[bb + q*4+3], y);
        }
        out[off] = fmaf(xv, Dd, y);
    }
}

// ---------------------------------------------------------------------------
// Inputs (metadata order): x, h, W_delta, W_dt, b_dt, A_log, W_B, W_C, D
// ---------------------------------------------------------------------------
extern "C" void kernel_launch(void* const* d_in, const int* in_sizes, int n_in,
                              void* d_out, int out_size)
{
    const float* x      = (const float*)d_in[0];
    const float* h      = (const float*)d_in[1];
    const float* Wdelta = (const float*)d_in[2];
    const float* Wdt    = (const float*)d_in[3];
    const float* bdt    = (const float*)d_in[4];
    const float* Alog   = (const float*)d_in[5];
    const float* WB     = (const float*)d_in[6];
    const float* WC     = (const float*)d_in[7];
    const float* Dv     = (const float*)d_in[8];
    float* out = (float*)d_out;

    k_gemm1<<<dim3(NMT, NKC), 192>>>(x, Wdelta, WB, WC);
    k_prep<<<(D_INNER * NSTATE + 255) / 256, 256>>>(Alog);
    k_reduce<<<(BATCH * NCOLS + 255) / 256, 256>>>();
    k_dt<<<dim3(BATCH / DT_MT, D_INNER / DT_NT, 2), 256>>>(Wdt);
    k_epi<<<dim3(BATCH / 32, D_INNER / 32), 256>>>(x, h, bdt, Dv, out);
}

// round 17
// speedup vs baseline: 1.6208x; 1.2539x over previous
#include <cuda_runtime.h>
#include <cuda_bf16.h>
#include <math.h>

#define BATCH   256
#define D_INNER 5120
#define DT_RANK 160
#define NSTATE  16
#define NCOLS   192           // 160 (W_delta) + 16 (W_B) + 16 (W_C)

#define G1_NKC  32            // gemm1 K chunks
#define G1_KC   160           // 32*160 = 5120

// ---- scratch (__device__ globals; no allocation) ---------------------------
__device__ __nv_bfloat16 g_xh [BATCH * D_INNER],  g_xl [BATCH * D_INNER];
__device__ __nv_bfloat16 g_wch[NCOLS * D_INNER],  g_wcl[NCOLS * D_INNER];   // [n][k]
__device__ __nv_bfloat16 g_wdh[D_INNER * DT_RANK], g_wdl[D_INNER * DT_RANK]; // [n][k]
__device__ float g_part[G1_NKC * BATCH * NCOLS];  // 6.3 MB
__device__ __nv_bfloat16 g_Th[BATCH * DT_RANK], g_Tl[BATCH * DT_RANK];
__device__ float g_Bp[BATCH * NSTATE], g_C[BATCH * NSTATE];
__device__ float g_A [D_INNER * NSTATE];          // -exp(A_log)
__device__ float g_dt[BATCH * D_INNER];           // softplus(T@W_dt + b)

// ---- helpers ---------------------------------------------------------------
__device__ __forceinline__ void mma_bf16(float* d,
                                         const unsigned* a,
                                         unsigned b0, unsigned b1)
{
    asm volatile(
        "mma.sync.aligned.m16n8k16.row.col.f32.bf16.bf16.f32 "
        "{%0,%1,%2,%3}, {%4,%5,%6,%7}, {%8,%9}, {%0,%1,%2,%3};"
        : "+f"(d[0]), "+f"(d[1]), "+f"(d[2]), "+f"(d[3])
        : "r"(a[0]), "r"(a[1]), "r"(a[2]), "r"(a[3]), "r"(b0), "r"(b1));
}

__device__ __forceinline__ void split2(float v, __nv_bfloat16& h, __nv_bfloat16& l)
{
    h = __float2bfloat16(v);
    l = __float2bfloat16(v - __bfloat162float(h));
}

// ---------------------------------------------------------------------------
// Prep: one launch, block-range regions.
//  [0,1280)      x -> g_xh/g_xl (float4 per thread)
//  [1280,2080)   W_delta [5120][160] -> transpose+split -> g_wch/l rows 0..159
//  [2080,2400)   W_B [5120][16]     -> rows 160..175
//  [2400,2720)   W_C [5120][16]     -> rows 176..191
//  [2720,3040)   A_log -> g_A = -exp(A_log)
//  [3040,3840)   W_dt [160][5120]   -> transpose+split -> g_wdh/l [5120][160]
// ---------------------------------------------------------------------------
__global__ __launch_bounds__(256)
void k_prep(const float* __restrict__ x,
            const float* __restrict__ Wd,
            const float* __restrict__ Wb,
            const float* __restrict__ Wc,
            const float* __restrict__ Wdt,
            const float* __restrict__ A_log)
{
    __shared__ float ts[32][33];
    const int b   = blockIdx.x;
    const int tid = threadIdx.x;

    if (b < 1280) {                                   // x split
        int i = b * 256 + tid;                        // float4 index
        float4 v = ((const float4*)x)[i];
        __nv_bfloat16 h0,h1,h2,h3,l0,l1,l2,l3;
        split2(v.x,h0,l0); split2(v.y,h1,l1); split2(v.z,h2,l2); split2(v.w,h3,l3);
        __nv_bfloat162 ph0 = __halves2bfloat162(h0,h1), ph1 = __halves2bfloat162(h2,h3);
        __nv_bfloat162 pl0 = __halves2bfloat162(l0,l1), pl1 = __halves2bfloat162(l2,l3);
        uint2 uh; uh.x = *(unsigned*)&ph0; uh.y = *(unsigned*)&ph1;
        uint2 ul; ul.x = *(unsigned*)&pl0; ul.y = *(unsigned*)&pl1;
        ((uint2*)g_xh)[i] = uh;
        ((uint2*)g_xl)[i] = ul;
    } else if (b < 2080) {                            // W_delta transpose
        int b2 = b - 1280;
        int nt = b2 / 160, kt = b2 % 160;             // 5 x 160 tiles
        int k0 = kt * 32, n0 = nt * 32;
        int tx = tid & 31, ty = tid >> 5;
        #pragma unroll
        for (int s = 0; s < 4; s++)
            ts[ty + 8*s][tx] = Wd[(size_t)(k0 + ty + 8*s) * DT_RANK + n0 + tx];
        __syncthreads();
        #pragma unroll
        for (int s = 0; s < 4; s++) {
            float v = ts[tx][ty + 8*s];
            __nv_bfloat16 h,l; split2(v,h,l);
            size_t o = (size_t)(n0 + ty + 8*s) * D_INNER + k0 + tx;
            g_wch[o] = h; g_wcl[o] = l;
        }
    } else if (b < 2400) {                            // W_B
        int i = (b - 2080) * 256 + tid;               // 81920
        int n = i / D_INNER, k = i % D_INNER;
        __nv_bfloat16 h,l; split2(Wb[(size_t)k * NSTATE + n], h, l);
        size_t o = (size_t)(160 + n) * D_INNER + k;
        g_wch[o] = h; g_wcl[o] = l;
    } else if (b < 2720) {                            // W_C
        int i = (b - 2400) * 256 + tid;
        int n = i / D_INNER, k = i % D_INNER;
        __nv_bfloat16 h,l; split2(Wc[(size_t)k * NSTATE + n], h, l);
        size_t o = (size_t)(176 + n) * D_INNER + k;
        g_wch[o] = h; g_wcl[o] = l;
    } else if (b < 3040) {                            // A = -exp(A_log)
        int i = (b - 2720) * 256 + tid;
        g_A[i] = -__expf(A_log[i]);
    } else {                                          // W_dt transpose
        int b2 = b - 3040;
        int nt = b2 / 5, kt = b2 % 5;                 // 160 x 5 tiles
        int k0 = kt * 32, n0 = nt * 32;
        int tx = tid & 31, ty = tid >> 5;
        #pragma unroll
        for (int s = 0; s < 4; s++)
            ts[ty + 8*s][tx] = Wdt[(size_t)(k0 + ty + 8*s) * D_INNER + n0 + tx];
        __syncthreads();
        #pragma unroll
        for (int s = 0; s < 4; s++) {
            float v = ts[tx][ty + 8*s];
            __nv_bfloat16 h,l; split2(v,h,l);
            size_t o = (size_t)(n0 + ty + 8*s) * DT_RANK + k0 + tx;
            g_wdh[o] = h; g_wdl[o] = l;
        }
    }
}

// ---------------------------------------------------------------------------
// GEMM1 (tensor core): P[kc] = x[:, kc*160:+160] @ Wcat^T  -> partials
// grid (4, 3, 32), block 128 (4 warps as 2m x 2n). Warp tile 32m x 32n.
// 3-pass bf16 split accumulate in fp32.
// ---------------------------------------------------------------------------
__global__ __launch_bounds__(128)
void k_gemm1()
{
    const int m0  = blockIdx.x * 64;
    const int n0  = blockIdx.y * 64;
    const int kc  = blockIdx.z;
    const int tid = threadIdx.x;
    const int wid = tid >> 5, lane = tid & 31;
    const int grp = lane >> 2, tig = lane & 3;
    const int wm  = (wid >> 1) * 32;
    const int wn  = (wid & 1) * 32;

    const unsigned* xh = (const unsigned*)g_xh;
    const unsigned* xl = (const unsigned*)g_xl;
    const unsigned* bh = (const unsigned*)g_wch;
    const unsigned* bl = (const unsigned*)g_wcl;
    const int RW = D_INNER / 2;          // u32 per row

    float acc[2][4][4];
    #pragma unroll
    for (int i = 0; i < 2; i++)
        #pragma unroll
        for (int j = 0; j < 4; j++)
            #pragma unroll
            for (int q = 0; q < 4; q++) acc[i][j][q] = 0.f;

    #pragma unroll 1
    for (int j = 0; j < G1_KC / 16; j++) {
        const int ks = kc * G1_KC + j * 16;
        unsigned ah[2][4], al[2][4], wbh[4][2], wbl[4][2];
        #pragma unroll
        for (int mf = 0; mf < 2; mf++) {
            size_t base = (size_t)(m0 + wm + mf*16 + grp) * RW + (ks >> 1) + tig;
            ah[mf][0] = xh[base];           al[mf][0] = xl[base];
            ah[mf][1] = xh[base + 8*RW];    al[mf][1] = xl[base + 8*RW];
            ah[mf][2] = xh[base + 4];       al[mf][2] = xl[base + 4];
            ah[mf][3] = xh[base + 4 + 8*RW];al[mf][3] = xl[base + 4 + 8*RW];
        }
        #pragma unroll
        for (int nf = 0; nf < 4; nf++) {
            size_t base = (size_t)(n0 + wn + nf*8 + grp) * RW + (ks >> 1) + tig;
            wbh[nf][0] = bh[base];     wbh[nf][1] = bh[base + 4];
            wbl[nf][0] = bl[base];     wbl[nf][1] = bl[base + 4];
        }
        #pragma unroll
        for (int mf = 0; mf < 2; mf++)
            #pragma unroll
            for (int nf = 0; nf < 4; nf++) {
                mma_bf16(acc[mf][nf], ah[mf], wbh[nf][0], wbh[nf][1]);
                mma_bf16(acc[mf][nf], ah[mf], wbl[nf][0], wbl[nf][1]);
                mma_bf16(acc[mf][nf], al[mf], wbh[nf][0], wbh[nf][1]);
            }
    }

    #pragma unroll
    for (int mf = 0; mf < 2; mf++)
        #pragma unroll
        for (int nf = 0; nf < 4; nf++) {
            int row = m0 + wm + mf*16 + grp;
            int col = n0 + wn + nf*8 + 2*tig;
            float* p0 = g_part + ((size_t)kc * BATCH + row) * NCOLS + col;
            *(float2*)p0                 = make_float2(acc[mf][nf][0], acc[mf][nf][1]);
            *(float2*)(p0 + 8 * NCOLS)   = make_float2(acc[mf][nf][2], acc[mf][nf][3]);
        }
}

// ---------------------------------------------------------------------------
// Reduce 32 K-chunk partials -> T (bf16 hi/lo) / Bp / C
// ---------------------------------------------------------------------------
__global__ __launch_bounds__(256)
void k_reduce()
{
    int idx = blockIdx.x * 256 + threadIdx.x;      // 49152
    if (idx >= BATCH * NCOLS) return;
    int row = idx / NCOLS;
    int n   = idx % NCOLS;
    float s = 0.f;
    #pragma unroll
    for (int c = 0; c < G1_NKC; c++)
        s += g_part[((size_t)c * BATCH + row) * NCOLS + n];
    if (n < DT_RANK) {
        __nv_bfloat16 h,l; split2(s,h,l);
        g_Th[row * DT_RANK + n] = h;
        g_Tl[row * DT_RANK + n] = l;
    }
    else if (n < DT_RANK + NSTATE) g_Bp[row * NSTATE + (n - DT_RANK)] = s;
    else                           g_C [row * NSTATE + (n - DT_RANK - NSTATE)] = s;
}

// ---------------------------------------------------------------------------
// GEMM2 (tensor core): dt = softplus(T @ W_dt + b_dt)
// grid (4, 80), block 128 (4 warps as 2m x 2n). K = 160 = 10 k-steps.
// ---------------------------------------------------------------------------
__global__ __launch_bounds__(128)
void k_dt(const float* __restrict__ b_dt)
{
    const int m0  = blockIdx.x * 64;
    const int n0  = blockIdx.y * 64;
    const int tid = threadIdx.x;
    const int wid = tid >> 5, lane = tid & 31;
    const int grp = lane >> 2, tig = lane & 3;
    const int wm  = (wid >> 1) * 32;
    const int wn  = (wid & 1) * 32;

    const unsigned* th = (const unsigned*)g_Th;
    const unsigned* tl = (const unsigned*)g_Tl;
    const unsigned* wh = (const unsigned*)g_wdh;
    const unsigned* wl = (const unsigned*)g_wdl;
    const int RW = DT_RANK / 2;          // 80 u32 per row

    float acc[2][4][4];
    #pragma unroll
    for (int i = 0; i < 2; i++)
        #pragma unroll
        for (int j = 0; j < 4; j++)
            #pragma unroll
            for (int q = 0; q < 4; q++) acc[i][j][q] = 0.f;

    #pragma unroll 1
    for (int j = 0; j < DT_RANK / 16; j++) {
        const int ks = j * 16;
        unsigned ah[2][4], al[2][4], wbh[4][2], wbl[4][2];
        #pragma unroll
        for (int mf = 0; mf < 2; mf++) {
            size_t base = (size_t)(m0 + wm + mf*16 + grp) * RW + (ks >> 1) + tig;
            ah[mf][0] = th[base];            al[mf][0] = tl[base];
            ah[mf][1] = th[base + 8*RW];     al[mf][1] = tl[base + 8*RW];
            ah[mf][2] = th[base + 4];        al[mf][2] = tl[base + 4];
            ah[mf][3] = th[base + 4 + 8*RW]; al[mf][3] = tl[base + 4 + 8*RW];
        }
        #pragma unroll
        for (int nf = 0; nf < 4; nf++) {
            size_t base = (size_t)(n0 + wn + nf*8 + grp) * RW + (ks >> 1) + tig;
            wbh[nf][0] = wh[base];     wbh[nf][1] = wh[base + 4];
            wbl[nf][0] = wl[base];     wbl[nf][1] = wl[base + 4];
        }
        #pragma unroll
        for (int mf = 0; mf < 2; mf++)
            #pragma unroll
            for (int nf = 0; nf < 4; nf++) {
                mma_bf16(acc[mf][nf], ah[mf], wbh[nf][0], wbh[nf][1]);
                mma_bf16(acc[mf][nf], ah[mf], wbl[nf][0], wbl[nf][1]);
                mma_bf16(acc[mf][nf], al[mf], wbh[nf][0], wbh[nf][1]);
            }
    }

    #pragma unroll
    for (int mf = 0; mf < 2; mf++)
        #pragma unroll
        for (int nf = 0; nf < 4; nf++) {
            int row = m0 + wm + mf*16 + grp;
            int col = n0 + wn + nf*8 + 2*tig;
            float2 bv = *(const float2*)(b_dt + col);
            float z0 = acc[mf][nf][0] + bv.x;
            float z1 = acc[mf][nf][1] + bv.y;
            float z2 = acc[mf][nf][2] + bv.x;
            float z3 = acc[mf][nf][3] + bv.y;
            z0 = (z0 > 20.f) ? z0 : log1pf(__expf(z0));
            z1 = (z1 > 20.f) ? z1 : log1pf(__expf(z1));
            z2 = (z2 > 20.f) ? z2 : log1pf(__expf(z2));
            z3 = (z3 > 20.f) ? z3 : log1pf(__expf(z3));
            float* p0 = g_dt + (size_t)row * D_INNER + col;
            *(float2*)p0                   = make_float2(z0, z1);
            *(float2*)(p0 + 8 * D_INNER)   = make_float2(z2, z3);
        }
}

// ---------------------------------------------------------------------------
// Streaming epilogue. grid (8, 160), block 256.
// ---------------------------------------------------------------------------
__global__ __launch_bounds__(256)
void k_epi(const float* __restrict__ x,
           const float* __restrict__ h,
           const float* __restrict__ Dv,
           float* __restrict__ out)
{
    __shared__ float Bsh[32 * NSTATE];
    __shared__ float Csh[32 * NSTATE];
    const int b0  = blockIdx.x * 32;
    const int d0  = blockIdx.y * 32;
    const int tid = threadIdx.x;
    const int dl  = tid & 31;
    const int bg  = tid >> 5;

    for (int i = tid; i < 32 * NSTATE; i += 256) {
        Bsh[i] = g_Bp[b0 * NSTATE + i];
        Csh[i] = g_C [b0 * NSTATE + i];
    }
    __syncthreads();

    const int d = d0 + dl;
    float a[NSTATE];
    #pragma unroll
    for (int q = 0; q < 4; q++) {
        float4 av = *(const float4*)(g_A + (size_t)d * NSTATE + q * 4);
        a[q * 4 + 0] = av.x; a[q * 4 + 1] = av.y;
        a[q * 4 + 2] = av.z; a[q * 4 + 3] = av.w;
    }
    const float Dd = Dv[d];

    #pragma unroll
    for (int i = 0; i < 4; i++) {
        const int b = b0 + bg * 4 + i;
        const size_t off = (size_t)b * D_INNER + d;
        const float dt  = g_dt[off];
        const float xv  = x[off];
        const float dtx = dt * xv;
        const float4* hp = (const float4*)(h + off * NSTATE);
        const int bb = (bg * 4 + i) * NSTATE;
        float y = 0.f;
        #pragma unroll
        for (int q = 0; q < 4; q++) {
            float4 h4 = hp[q];
            float hn;
            hn = fmaf(__expf(dt * a[q*4+0]), h4.x, dtx * Bsh[bb + q*4+0]); y = fmaf(hn, Csh[bb + q*4+0], y);
            hn = fmaf(__expf(dt * a[q*4+1]), h4.y, dtx * Bsh[bb + q*4+1]); y = fmaf(hn, Csh[bb + q*4+1], y);
            hn = fmaf(__expf(dt * a[q*4+2]), h4.z, dtx * Bsh[bb + q*4+2]); y = fmaf(hn, Csh[bb + q*4+2], y);
            hn = fmaf(__expf(dt * a[q*4+3]), h4.w, dtx * Bsh[bb + q*4+3]); y = fmaf(hn, Csh[bb + q*4+3], y);
        }
        out[off] = fmaf(xv, Dd, y);
    }
}

// ---------------------------------------------------------------------------
// Inputs (metadata order): x, h, W_delta, W_dt, b_dt, A_log, W_B, W_C, D
// ---------------------------------------------------------------------------
extern "C" void kernel_launch(void* const* d_in, const int* in_sizes, int n_in,
                              void* d_out, int out_size)
{
    const float* x      = (const float*)d_in[0];
    const float* h      = (const float*)d_in[1];
    const float* Wdelta = (const float*)d_in[2];
    const float* Wdt    = (const float*)d_in[3];
    const float* bdt    = (const float*)d_in[4];
    const float* Alog   = (const float*)d_in[5];
    const float* WB     = (const float*)d_in[6];
    const float* WC     = (const float*)d_in[7];
    const float* Dv     = (const float*)d_in[8];
    float* out = (float*)d_out;

    k_prep<<<3840, 256>>>(x, Wdelta, WB, WC, Wdt, Alog);
    k_gemm1<<<dim3(4, 3, G1_NKC), 128>>>();
    k_reduce<<<(BATCH * NCOLS + 255) / 256, 256>>>();
    k_dt<<<dim3(4, 80), 128>>>(bdt);
    k_epi<<<dim3(BATCH / 32, D_INNER / 32), 256>>>(x, h, Dv, out);
}